// round 1
// baseline (speedup 1.0000x reference)
#include <cuda_runtime.h>
#include <math.h>

// Problem constants (fixed shapes from reference)
#define Nn   100000
#define Ee   600000
#define INC  128
#define OC   128     // H*C
#define Hh   2
#define MSGd 64
#define Td   64

// ---------------- scratch (device globals; no runtime alloc) ----------------
__device__ __align__(16) float g_q[(size_t)Nn * OC];
__device__ __align__(16) float g_k[(size_t)Nn * OC];
__device__ __align__(16) float g_v[(size_t)Nn * OC];
__device__ __align__(16) float g_e[(size_t)Ee * OC];
__device__ __align__(16) float g_acc[(size_t)Nn * OC];
__device__ float g_denom[(size_t)Nn * Hh];

// ---------------------------------------------------------------------------
// K1: node GEMMs.  out_j = x @ W_j + b_j for j in {q,k,v,skip}.
// 128-row tile per block, K=128 fully resident in shared, 256 threads,
// each thread computes an 8x8 micro-tile split as rows {4ty..}+{64+4ty..},
// cols {4tx..}+{64+4tx..} (conflict-free 128-bit LDS).
// ---------------------------------------------------------------------------
#define SXT_STRIDE 132
#define SMEM1_BYTES ((128*SXT_STRIDE + 128*128 + 128) * 4)

__global__ __launch_bounds__(256, 1)
void node_gemm(const float* __restrict__ x,
               const float* __restrict__ Wq, const float* __restrict__ bq,
               const float* __restrict__ Wk, const float* __restrict__ bk,
               const float* __restrict__ Wv, const float* __restrict__ bv,
               const float* __restrict__ Wsk, const float* __restrict__ bsk,
               float* __restrict__ out_skip)
{
    extern __shared__ float sm[];
    float* sxT = sm;                       // [128][SXT_STRIDE] : x tile, k-major
    float* sw  = sm + 128 * SXT_STRIDE;    // [128][128] : weight, k-major
    float* sb  = sw + 128 * 128;           // [128] bias

    const int tid = threadIdx.x;
    const int m0  = blockIdx.x * 128;

    // Load x tile (transposed into k-major)
    {
        const int c4 = tid & 31;    // float4 column within row
        const int r0 = tid >> 5;    // 0..7
        #pragma unroll
        for (int it = 0; it < 16; ++it) {
            const int row = r0 + it * 8;
            const int m   = m0 + row;
            float4 vv = make_float4(0.f, 0.f, 0.f, 0.f);
            if (m < Nn) vv = *(const float4*)(x + (size_t)m * INC + c4 * 4);
            sxT[(c4 * 4 + 0) * SXT_STRIDE + row] = vv.x;
            sxT[(c4 * 4 + 1) * SXT_STRIDE + row] = vv.y;
            sxT[(c4 * 4 + 2) * SXT_STRIDE + row] = vv.z;
            sxT[(c4 * 4 + 3) * SXT_STRIDE + row] = vv.w;
        }
    }

    const int tx = tid & 15;
    const int ty = tid >> 4;

    const float* Ws[4]   = {Wq, Wk, Wv, Wsk};
    const float* bs[4]   = {bq, bk, bv, bsk};
    float*       outs[4] = {g_q, g_k, g_v, out_skip};

    #pragma unroll 1
    for (int j = 0; j < 4; ++j) {
        __syncthreads();
        {
            const float4* Wsrc = (const float4*)Ws[j];
            #pragma unroll
            for (int i = tid; i < 128 * 128 / 4; i += 256)
                ((float4*)sw)[i] = Wsrc[i];
            if (tid < 128) sb[tid] = bs[j][tid];
        }
        __syncthreads();

        float acc[8][8];
        #pragma unroll
        for (int r = 0; r < 8; ++r)
            #pragma unroll
            for (int c = 0; c < 8; ++c) acc[r][c] = 0.f;

        #pragma unroll 4
        for (int k = 0; k < 128; ++k) {
            float4 a0 = *(const float4*)&sxT[k * SXT_STRIDE + ty * 4];
            float4 a1 = *(const float4*)&sxT[k * SXT_STRIDE + 64 + ty * 4];
            float4 b0 = *(const float4*)&sw[k * 128 + tx * 4];
            float4 b1 = *(const float4*)&sw[k * 128 + 64 + tx * 4];
            float a[8] = {a0.x, a0.y, a0.z, a0.w, a1.x, a1.y, a1.z, a1.w};
            float b[8] = {b0.x, b0.y, b0.z, b0.w, b1.x, b1.y, b1.z, b1.w};
            #pragma unroll
            for (int r = 0; r < 8; ++r)
                #pragma unroll
                for (int c = 0; c < 8; ++c)
                    acc[r][c] += a[r] * b[c];
        }

        float* outp = outs[j];
        #pragma unroll
        for (int ri = 0; ri < 8; ++ri) {
            const int row = (ri < 4) ? (ty * 4 + ri) : (64 + ty * 4 + (ri - 4));
            const int m = m0 + row;
            if (m < Nn) {
                float4 o0, o1;
                o0.x = acc[ri][0] + sb[tx * 4 + 0];
                o0.y = acc[ri][1] + sb[tx * 4 + 1];
                o0.z = acc[ri][2] + sb[tx * 4 + 2];
                o0.w = acc[ri][3] + sb[tx * 4 + 3];
                o1.x = acc[ri][4] + sb[64 + tx * 4 + 0];
                o1.y = acc[ri][5] + sb[64 + tx * 4 + 1];
                o1.z = acc[ri][6] + sb[64 + tx * 4 + 2];
                o1.w = acc[ri][7] + sb[64 + tx * 4 + 3];
                *(float4*)(outp + (size_t)m * OC + tx * 4)      = o0;
                *(float4*)(outp + (size_t)m * OC + 64 + tx * 4) = o1;
            }
        }
    }
}

// ---------------------------------------------------------------------------
// K2a: edge GEMM.  attr = [cos(rel_t*wt+bt) | msg]  (built in smem),
// g_e = attr @ We.  Tile: 128 edges x 128.
// ---------------------------------------------------------------------------
#define SA_STRIDE 129
#define SMEM2_BYTES ((128*SA_STRIDE + 128*128) * 4)

__global__ __launch_bounds__(256, 1)
void edge_gemm(const float* __restrict__ lu, const int* __restrict__ ei,
               const float* __restrict__ tt, const float* __restrict__ msg,
               const float* __restrict__ wt, const float* __restrict__ bt,
               const float* __restrict__ We)
{
    extern __shared__ float sm[];
    float* sA = sm;                    // [128 edges][SA_STRIDE] attr, edge-major
    float* sw = sm + 128 * SA_STRIDE;  // [128][128] We, k-major
    __shared__ float srel[128];

    const int tid = threadIdx.x;
    const int e0  = blockIdx.x * 128;

    // Load We
    {
        const float4* Wsrc = (const float4*)We;
        #pragma unroll
        for (int i = tid; i < 128 * 128 / 4; i += 256)
            ((float4*)sw)[i] = Wsrc[i];
    }
    // rel_t per edge
    if (tid < 128) {
        const int e = e0 + tid;
        float r = 0.f;
        if (e < Ee) {
            const int s = ei[e];
            r = lu[s] - tt[e];
        }
        srel[tid] = r;
    }
    __syncthreads();

    // time-encoding half of attr
    #pragma unroll
    for (int i = tid; i < 128 * 64; i += 256) {
        const int eg = i >> 6, d = i & 63;
        sA[eg * SA_STRIDE + d] = cosf(srel[eg] * wt[d] + bt[d]);
    }
    // msg half of attr
    #pragma unroll
    for (int i = tid; i < 128 * 64; i += 256) {
        const int eg = i >> 6, d = i & 63;
        const int e = e0 + eg;
        sA[eg * SA_STRIDE + 64 + d] = (e < Ee) ? msg[(size_t)e * MSGd + d] : 0.f;
    }
    __syncthreads();

    const int tx = tid & 15;
    const int ty = tid >> 4;

    float acc[8][8];
    #pragma unroll
    for (int r = 0; r < 8; ++r)
        #pragma unroll
        for (int c = 0; c < 8; ++c) acc[r][c] = 0.f;

    const int row_lo = ty * 4;
    const int row_hi = 64 + ty * 4;

    #pragma unroll 4
    for (int k = 0; k < 128; ++k) {
        float a[8];
        #pragma unroll
        for (int i = 0; i < 4; ++i) {
            a[i]     = sA[(row_lo + i) * SA_STRIDE + k];
            a[i + 4] = sA[(row_hi + i) * SA_STRIDE + k];
        }
        float4 b0 = *(const float4*)&sw[k * 128 + tx * 4];
        float4 b1 = *(const float4*)&sw[k * 128 + 64 + tx * 4];
        float b[8] = {b0.x, b0.y, b0.z, b0.w, b1.x, b1.y, b1.z, b1.w};
        #pragma unroll
        for (int r = 0; r < 8; ++r)
            #pragma unroll
            for (int c = 0; c < 8; ++c)
                acc[r][c] += a[r] * b[c];
    }

    #pragma unroll
    for (int ri = 0; ri < 8; ++ri) {
        const int row = (ri < 4) ? (ty * 4 + ri) : (64 + ty * 4 + (ri - 4));
        const int e = e0 + row;
        if (e < Ee) {
            float4 o0 = make_float4(acc[ri][0], acc[ri][1], acc[ri][2], acc[ri][3]);
            float4 o1 = make_float4(acc[ri][4], acc[ri][5], acc[ri][6], acc[ri][7]);
            *(float4*)(g_e + (size_t)e * OC + tx * 4)      = o0;
            *(float4*)(g_e + (size_t)e * OC + 64 + tx * 4) = o1;
        }
    }
}

// ---------------------------------------------------------------------------
// K2b: per-edge attention + scatter.  One warp per edge.
// alpha_h = q_i . (k_j + e) / 8 ; w = exp(alpha) (no max-shift needed, see
// analysis: |alpha| <~ 8).  Accumulate w and w*(v_j+e) via atomics.
// ---------------------------------------------------------------------------
__global__ __launch_bounds__(256)
void edge_attn(const int* __restrict__ ei)
{
    const int gw   = (blockIdx.x * blockDim.x + threadIdx.x) >> 5;
    const int lane = threadIdx.x & 31;
    if (gw >= Ee) return;
    const int e   = gw;
    const int src = ei[e];
    const int dst = ei[Ee + e];

    const float4 e4 = *(const float4*)(g_e + (size_t)e   * OC + lane * 4);
    const float4 k4 = *(const float4*)(g_k + (size_t)src * OC + lane * 4);
    const float4 v4 = *(const float4*)(g_v + (size_t)src * OC + lane * 4);
    const float4 q4 = *(const float4*)(g_q + (size_t)dst * OC + lane * 4);

    const float kjx = k4.x + e4.x, kjy = k4.y + e4.y;
    const float kjz = k4.z + e4.z, kjw = k4.w + e4.w;

    float p = q4.x * kjx + q4.y * kjy + q4.z * kjz + q4.w * kjw;
    // reduce within each 16-lane half (one head per half)
    p += __shfl_xor_sync(0xffffffffu, p, 8);
    p += __shfl_xor_sync(0xffffffffu, p, 4);
    p += __shfl_xor_sync(0xffffffffu, p, 2);
    p += __shfl_xor_sync(0xffffffffu, p, 1);

    const float w = __expf(p * 0.125f);   // 1/sqrt(64)

    if ((lane & 15) == 0)
        atomicAdd(&g_denom[2 * dst + (lane >> 4)], w);

    float* ap = g_acc + (size_t)dst * OC + lane * 4;
    atomicAdd(ap + 0, w * (v4.x + e4.x));
    atomicAdd(ap + 1, w * (v4.y + e4.y));
    atomicAdd(ap + 2, w * (v4.z + e4.z));
    atomicAdd(ap + 3, w * (v4.w + e4.w));
}

// ---------------------------------------------------------------------------
// K3: out = g_acc / (denom + 1e-16) + skip (skip already in d_out from K1)
// ---------------------------------------------------------------------------
__global__ __launch_bounds__(256)
void finalize(float* __restrict__ out)
{
    const int i = blockIdx.x * blockDim.x + threadIdx.x;   // float4 index
    if (i >= Nn * OC / 4) return;
    const int n = i >> 5;
    const int h = (i >> 4) & 1;
    const float inv = 1.f / (g_denom[2 * n + h] + 1e-16f);
    float4 a = ((const float4*)g_acc)[i];
    float4 o = ((float4*)out)[i];
    o.x += a.x * inv;
    o.y += a.y * inv;
    o.z += a.z * inv;
    o.w += a.w * inv;
    ((float4*)out)[i] = o;
}

// ---------------------------------------------------------------------------
extern "C" void kernel_launch(void* const* d_in, const int* in_sizes, int n_in,
                              void* d_out, int out_size)
{
    const float* x    = (const float*)d_in[0];
    const float* lu   = (const float*)d_in[1];
    const int*   ei   = (const int*)  d_in[2];
    const float* tt   = (const float*)d_in[3];
    const float* msg  = (const float*)d_in[4];
    const float* wt   = (const float*)d_in[5];
    const float* bt   = (const float*)d_in[6];
    const float* Wq   = (const float*)d_in[7];
    const float* bq   = (const float*)d_in[8];
    const float* Wk   = (const float*)d_in[9];
    const float* bk   = (const float*)d_in[10];
    const float* Wv   = (const float*)d_in[11];
    const float* bv   = (const float*)d_in[12];
    const float* We   = (const float*)d_in[13];
    const float* Wsk  = (const float*)d_in[14];
    const float* bsk  = (const float*)d_in[15];
    float* out = (float*)d_out;

    cudaFuncSetAttribute(node_gemm, cudaFuncAttributeMaxDynamicSharedMemorySize, SMEM1_BYTES);
    cudaFuncSetAttribute(edge_gemm, cudaFuncAttributeMaxDynamicSharedMemorySize, SMEM2_BYTES);

    void* accp = nullptr;
    void* denp = nullptr;
    cudaGetSymbolAddress(&accp, g_acc);
    cudaGetSymbolAddress(&denp, g_denom);
    cudaMemsetAsync(accp, 0, (size_t)Nn * OC * sizeof(float));
    cudaMemsetAsync(denp, 0, (size_t)Nn * Hh * sizeof(float));

    node_gemm<<<(Nn + 127) / 128, 256, SMEM1_BYTES>>>(
        x, Wq, bq, Wk, bk, Wv, bv, Wsk, bsk, out);

    edge_gemm<<<(Ee + 127) / 128, 256, SMEM2_BYTES>>>(
        lu, ei, tt, msg, wt, bt, We);

    edge_attn<<<(Ee * 32 + 255) / 256, 256>>>(ei);

    finalize<<<(Nn * OC / 4 + 255) / 256, 256>>>(out);
}

// round 2
// speedup vs baseline: 1.0854x; 1.0854x over previous
#include <cuda_runtime.h>
#include <math.h>

// Problem constants (fixed shapes from reference)
#define Nn   100000
#define Ee   600000
#define INC  128
#define OC   128     // H*C
#define Hh   2
#define MSGd 64
#define Td   64

// ---------------- scratch (device globals; no runtime alloc) ----------------
__device__ __align__(16) float g_q[(size_t)Nn * OC];
__device__ __align__(16) float g_k[(size_t)Nn * OC];
__device__ __align__(16) float g_v[(size_t)Nn * OC];
__device__ __align__(16) float g_e[(size_t)Ee * OC];
__device__ __align__(16) float g_acc[(size_t)Nn * OC];
__device__ float g_denom[(size_t)Nn * Hh];
__device__ __align__(16) float g_WT[5 * 128 * 128];   // Wq^T,Wk^T,Wv^T,Wskip^T,We^T

// f32x2 packed FMA: d = a*b + d (lanewise on packed fp32 pairs)
__device__ __forceinline__ void fma2(unsigned long long& d,
                                     unsigned long long a,
                                     unsigned long long b)
{
    asm("fma.rn.f32x2 %0, %1, %2, %0;" : "+l"(d) : "l"(a), "l"(b));
}

__device__ __forceinline__ float ull_sum2(unsigned long long v)
{
    float lo, hi;
    asm("mov.b64 {%0, %1}, %2;" : "=f"(lo), "=f"(hi) : "l"(v));
    return lo + hi;
}

// ---------------------------------------------------------------------------
// K0: transpose all weight matrices once: g_WT[m][c][k] = W_m[k][c]
// ---------------------------------------------------------------------------
__global__ void transpose_weights(const float* __restrict__ Wq,
                                  const float* __restrict__ Wk,
                                  const float* __restrict__ Wv,
                                  const float* __restrict__ Wsk,
                                  const float* __restrict__ We)
{
    const float* src[5] = {Wq, Wk, Wv, Wsk, We};
    const float* S = src[blockIdx.y];
    float* D = g_WT + (size_t)blockIdx.y * 128 * 128;
    const int i = blockIdx.x * 256 + threadIdx.x;   // 0..16383
    const int k = i >> 7, c = i & 127;
    D[c * 128 + k] = S[k * 128 + c];
}

// ---------------------------------------------------------------------------
// Shared-memory layout for GEMMs:
//   sA  : [128 rows][128 k]  row-major fp32 (A tile; broadcast reads)
//   swT : [128 cols][132 k]  W^T, padded stride 132 (16B aligned, bank-free
//         for the tx+16j column mapping: lane bank step = 132 mod 32 = 4)
//   sb  : [128] bias
// ---------------------------------------------------------------------------
#define SWT_STRIDE 132
#define SMEM_GEMM_BYTES ((128*128 + 128*SWT_STRIDE + 128) * 4)

// Main f32x2 micro-kernel: 256 threads, thread (tx,ty) computes rows
// {ty*4+i, 64+ty*4+i} x cols {tx+16j}.  acc[r][j] packs even/odd-k partial
// sums in the two f32 lanes; collapsed at epilogue.
__device__ __forceinline__ void gemm_tile_f32x2(
    const float* __restrict__ sA, const float* __restrict__ swT,
    unsigned long long (&acc)[8][8], int tx, int ty)
{
    #pragma unroll
    for (int r = 0; r < 8; ++r)
        #pragma unroll
        for (int j = 0; j < 8; ++j) acc[r][j] = 0ull;

    #pragma unroll 2
    for (int k0 = 0; k0 < 128; k0 += 4) {
        ulonglong2 av[8];
        #pragma unroll
        for (int r = 0; r < 4; ++r) {
            av[r]     = *(const ulonglong2*)&sA[(ty * 4 + r) * 128 + k0];
            av[4 + r] = *(const ulonglong2*)&sA[(64 + ty * 4 + r) * 128 + k0];
        }
        #pragma unroll
        for (int jh = 0; jh < 2; ++jh) {
            ulonglong2 bv[4];
            #pragma unroll
            for (int j = 0; j < 4; ++j)
                bv[j] = *(const ulonglong2*)&swT[(tx + 16 * (jh * 4 + j)) * SWT_STRIDE + k0];
            #pragma unroll
            for (int r = 0; r < 8; ++r)
                #pragma unroll
                for (int j = 0; j < 4; ++j) {
                    fma2(acc[r][jh * 4 + j], av[r].x, bv[j].x);
                    fma2(acc[r][jh * 4 + j], av[r].y, bv[j].y);
                }
        }
    }
}

// ---------------------------------------------------------------------------
// K1: node GEMMs.  out_j = x @ W_j + b_j for j in {q,k,v,skip}.
// ---------------------------------------------------------------------------
__global__ __launch_bounds__(256, 1)
void node_gemm(const float* __restrict__ x,
               const float* __restrict__ bq, const float* __restrict__ bk,
               const float* __restrict__ bv, const float* __restrict__ bsk,
               float* __restrict__ out_skip)
{
    extern __shared__ float sm[];
    float* sA  = sm;                       // [128][128] x tile row-major
    float* swT = sm + 128 * 128;           // [128][132]
    float* sb  = swT + 128 * SWT_STRIDE;   // [128]

    const int tid = threadIdx.x;
    const int m0  = blockIdx.x * 128;
    const int tx  = tid & 15;
    const int ty  = tid >> 4;

    // Load x tile row-major (coalesced, conflict-free)
    #pragma unroll
    for (int it = 0; it < 16; ++it) {
        const int i4  = tid + it * 256;          // 0..4095
        const int row = i4 >> 5;
        const int k4  = (i4 & 31) * 4;
        const int m   = m0 + row;
        float4 vv = make_float4(0.f, 0.f, 0.f, 0.f);
        if (m < Nn) vv = *(const float4*)(x + (size_t)m * INC + k4);
        *(float4*)&sA[row * 128 + k4] = vv;
    }

    const float* bs[4]   = {bq, bk, bv, bsk};
    float*       outs[4] = {g_q, g_k, g_v, out_skip};

    #pragma unroll 1
    for (int j = 0; j < 4; ++j) {
        __syncthreads();
        {   // load W^T[j] into swT (padded stride)
            const float* D = g_WT + (size_t)j * 128 * 128;
            #pragma unroll
            for (int it = 0; it < 16; ++it) {
                const int i4 = tid + it * 256;
                const int c  = i4 >> 5;
                const int k4 = (i4 & 31) * 4;
                *(float4*)&swT[c * SWT_STRIDE + k4] = *(const float4*)&D[c * 128 + k4];
            }
            if (tid < 128) sb[tid] = bs[j][tid];
        }
        __syncthreads();

        unsigned long long acc[8][8];
        gemm_tile_f32x2(sA, swT, acc, tx, ty);

        float* outp = outs[j];
        #pragma unroll
        for (int r = 0; r < 8; ++r) {
            const int row = (r < 4) ? (ty * 4 + r) : (64 + ty * 4 + (r - 4));
            const int m = m0 + row;
            if (m < Nn) {
                #pragma unroll
                for (int jj = 0; jj < 8; ++jj) {
                    const int col = tx + 16 * jj;
                    outp[(size_t)m * OC + col] = ull_sum2(acc[r][jj]) + sb[col];
                }
            }
        }
    }
}

// ---------------------------------------------------------------------------
// K2a: edge GEMM.  attr = [cos(rel_t*wt+bt) | msg] built in smem,
// g_e = attr @ We.  128 edges per block.
// ---------------------------------------------------------------------------
__global__ __launch_bounds__(256, 1)
void edge_gemm(const float* __restrict__ lu, const int* __restrict__ ei,
               const float* __restrict__ tt, const float* __restrict__ msg,
               const float* __restrict__ wt, const float* __restrict__ bt)
{
    extern __shared__ float sm[];
    float* sA  = sm;                       // [128 edges][128] attr row-major
    float* swT = sm + 128 * 128;           // [128][132] We^T
    __shared__ float srel[128];

    const int tid = threadIdx.x;
    const int e0  = blockIdx.x * 128;
    const int tx  = tid & 15;
    const int ty  = tid >> 4;

    // Load We^T
    #pragma unroll
    for (int it = 0; it < 16; ++it) {
        const int i4 = tid + it * 256;
        const int c  = i4 >> 5;
        const int k4 = (i4 & 31) * 4;
        const float* D = g_WT + (size_t)4 * 128 * 128;
        *(float4*)&swT[c * SWT_STRIDE + k4] = *(const float4*)&D[c * 128 + k4];
    }
    // rel_t per edge
    if (tid < 128) {
        const int e = e0 + tid;
        float r = 0.f;
        if (e < Ee) {
            const int s = ei[e];
            r = lu[s] - tt[e];
        }
        srel[tid] = r;
    }
    __syncthreads();

    // time-encoding half of attr
    #pragma unroll
    for (int i = tid; i < 128 * 64; i += 256) {
        const int eg = i >> 6, d = i & 63;
        sA[eg * 128 + d] = cosf(srel[eg] * wt[d] + bt[d]);
    }
    // msg half of attr (float4)
    #pragma unroll
    for (int it = 0; it < 8; ++it) {
        const int i4 = tid + it * 256;       // 0..2047
        const int eg = i4 >> 4;
        const int p4 = (i4 & 15) * 4;
        const int e  = e0 + eg;
        float4 vv = make_float4(0.f, 0.f, 0.f, 0.f);
        if (e < Ee) vv = *(const float4*)(msg + (size_t)e * MSGd + p4);
        *(float4*)&sA[eg * 128 + 64 + p4] = vv;
    }
    __syncthreads();

    unsigned long long acc[8][8];
    gemm_tile_f32x2(sA, swT, acc, tx, ty);

    #pragma unroll
    for (int r = 0; r < 8; ++r) {
        const int row = (r < 4) ? (ty * 4 + r) : (64 + ty * 4 + (r - 4));
        const int e = e0 + row;
        if (e < Ee) {
            #pragma unroll
            for (int jj = 0; jj < 8; ++jj)
                g_e[(size_t)e * OC + tx + 16 * jj] = ull_sum2(acc[r][jj]);
        }
    }
}

// ---------------------------------------------------------------------------
// K2b: per-edge attention + scatter.  One warp per edge.
// alpha_h = q_i . (k_j + e) / 8 ; w = exp(alpha) (no max-shift: |alpha| small).
// Accumulate w and w*(v_j+e) via vectorized reductions (red.v4).
// ---------------------------------------------------------------------------
__global__ __launch_bounds__(256)
void edge_attn(const int* __restrict__ ei)
{
    const int gw   = (blockIdx.x * blockDim.x + threadIdx.x) >> 5;
    const int lane = threadIdx.x & 31;
    if (gw >= Ee) return;
    const int e   = gw;
    const int src = ei[e];
    const int dst = ei[Ee + e];

    const float4 e4 = __ldcs((const float4*)(g_e + (size_t)e * OC + lane * 4));
    const float4 k4 = *(const float4*)(g_k + (size_t)src * OC + lane * 4);
    const float4 v4 = *(const float4*)(g_v + (size_t)src * OC + lane * 4);
    const float4 q4 = *(const float4*)(g_q + (size_t)dst * OC + lane * 4);

    const float kjx = k4.x + e4.x, kjy = k4.y + e4.y;
    const float kjz = k4.z + e4.z, kjw = k4.w + e4.w;

    float p = q4.x * kjx + q4.y * kjy + q4.z * kjz + q4.w * kjw;
    // reduce within each 16-lane half (one head per half)
    p += __shfl_xor_sync(0xffffffffu, p, 8);
    p += __shfl_xor_sync(0xffffffffu, p, 4);
    p += __shfl_xor_sync(0xffffffffu, p, 2);
    p += __shfl_xor_sync(0xffffffffu, p, 1);

    const float w = __expf(p * 0.125f);   // 1/sqrt(64)

    if ((lane & 15) == 0)
        atomicAdd(&g_denom[2 * dst + (lane >> 4)], w);

    float* ap = g_acc + (size_t)dst * OC + lane * 4;
    const float wx = w * (v4.x + e4.x);
    const float wy = w * (v4.y + e4.y);
    const float wz = w * (v4.z + e4.z);
    const float ww = w * (v4.w + e4.w);
    asm volatile("red.global.add.v4.f32 [%0], {%1, %2, %3, %4};"
                 :: "l"(ap), "f"(wx), "f"(wy), "f"(wz), "f"(ww) : "memory");
}

// ---------------------------------------------------------------------------
// K3: out = g_acc / (denom + 1e-16) + skip (skip already in d_out from K1)
// ---------------------------------------------------------------------------
__global__ __launch_bounds__(256)
void finalize(float* __restrict__ out)
{
    const int i = blockIdx.x * blockDim.x + threadIdx.x;   // float4 index
    if (i >= Nn * OC / 4) return;
    const int n = i >> 5;
    const int h = (i >> 4) & 1;
    const float inv = 1.f / (g_denom[2 * n + h] + 1e-16f);
    float4 a = ((const float4*)g_acc)[i];
    float4 o = ((float4*)out)[i];
    o.x += a.x * inv;
    o.y += a.y * inv;
    o.z += a.z * inv;
    o.w += a.w * inv;
    ((float4*)out)[i] = o;
}

// ---------------------------------------------------------------------------
extern "C" void kernel_launch(void* const* d_in, const int* in_sizes, int n_in,
                              void* d_out, int out_size)
{
    const float* x    = (const float*)d_in[0];
    const float* lu   = (const float*)d_in[1];
    const int*   ei   = (const int*)  d_in[2];
    const float* tt   = (const float*)d_in[3];
    const float* msg  = (const float*)d_in[4];
    const float* wt   = (const float*)d_in[5];
    const float* bt   = (const float*)d_in[6];
    const float* Wq   = (const float*)d_in[7];
    const float* bq   = (const float*)d_in[8];
    const float* Wk   = (const float*)d_in[9];
    const float* bk   = (const float*)d_in[10];
    const float* Wv   = (const float*)d_in[11];
    const float* bv   = (const float*)d_in[12];
    const float* We   = (const float*)d_in[13];
    const float* Wsk  = (const float*)d_in[14];
    const float* bsk  = (const float*)d_in[15];
    float* out = (float*)d_out;

    cudaFuncSetAttribute(node_gemm, cudaFuncAttributeMaxDynamicSharedMemorySize, SMEM_GEMM_BYTES);
    cudaFuncSetAttribute(edge_gemm, cudaFuncAttributeMaxDynamicSharedMemorySize, SMEM_GEMM_BYTES);

    void* accp = nullptr;
    void* denp = nullptr;
    cudaGetSymbolAddress(&accp, g_acc);
    cudaGetSymbolAddress(&denp, g_denom);
    cudaMemsetAsync(accp, 0, (size_t)Nn * OC * sizeof(float));
    cudaMemsetAsync(denp, 0, (size_t)Nn * Hh * sizeof(float));

    dim3 tg(64, 5);
    transpose_weights<<<tg, 256>>>(Wq, Wk, Wv, Wsk, We);

    node_gemm<<<(Nn + 127) / 128, 256, SMEM_GEMM_BYTES>>>(
        x, bq, bk, bv, bsk, out);

    edge_gemm<<<(Ee + 127) / 128, 256, SMEM_GEMM_BYTES>>>(
        lu, ei, tt, msg, wt, bt);

    edge_attn<<<(Ee * 32 + 255) / 256, 256>>>(ei);

    finalize<<<(Nn * OC / 4 + 255) / 256, 256>>>(out);
}

// round 3
// speedup vs baseline: 1.9944x; 1.8375x over previous
#include <cuda_runtime.h>
#include <cuda_bf16.h>
#include <math.h>
#include <stdint.h>

// Problem constants (fixed shapes from reference)
#define Nn   100000
#define Ee   600000
#define INC  128
#define OC   128     // H*C
#define Hh   2
#define MSGd 64
#define Td   64

#define SP   136     // smem bf16 row stride (272B: conflict-free ldmatrix)

// ---------------- scratch (device globals; no runtime alloc) ----------------
__device__ __align__(16) float g_q[(size_t)Nn * OC];
__device__ __align__(16) float g_k[(size_t)Nn * OC];
__device__ __align__(16) float g_v[(size_t)Nn * OC];
__device__ __align__(16) float g_e[(size_t)Ee * OC];
__device__ __align__(16) float g_acc[(size_t)Nn * OC];
__device__ float g_denom[(size_t)Nn * Hh];
// bf16 hi/lo split weights, native [k][n] layout: Wq,Wk,Wv,Wskip,We
__device__ __align__(16) __nv_bfloat16 g_Wh[5 * 128 * 128];
__device__ __align__(16) __nv_bfloat16 g_Wl[5 * 128 * 128];

// ---------------------------------------------------------------------------
// helpers
// ---------------------------------------------------------------------------
__device__ __forceinline__ uint32_t smem_u32(const void* p)
{
    return (uint32_t)__cvta_generic_to_shared(p);
}

__device__ __forceinline__ void split_bf16(float v, __nv_bfloat16& h, __nv_bfloat16& l)
{
    h = __float2bfloat16(v);
    l = __float2bfloat16(v - __bfloat162float(h));
}

__device__ __forceinline__ void ldsm4(uint32_t* r, uint32_t a)
{
    asm volatile("ldmatrix.sync.aligned.m8n8.x4.shared.b16 {%0,%1,%2,%3},[%4];"
                 : "=r"(r[0]), "=r"(r[1]), "=r"(r[2]), "=r"(r[3]) : "r"(a));
}
__device__ __forceinline__ void ldsm4t(uint32_t* r, uint32_t a)
{
    asm volatile("ldmatrix.sync.aligned.m8n8.x4.trans.shared.b16 {%0,%1,%2,%3},[%4];"
                 : "=r"(r[0]), "=r"(r[1]), "=r"(r[2]), "=r"(r[3]) : "r"(a));
}
__device__ __forceinline__ void mma16816(float* c, const uint32_t* a,
                                         uint32_t b0, uint32_t b1)
{
    asm volatile(
        "mma.sync.aligned.m16n8k16.row.col.f32.bf16.bf16.f32 "
        "{%0,%1,%2,%3},{%4,%5,%6,%7},{%8,%9},{%0,%1,%2,%3};"
        : "+f"(c[0]), "+f"(c[1]), "+f"(c[2]), "+f"(c[3])
        : "r"(a[0]), "r"(a[1]), "r"(a[2]), "r"(a[3]), "r"(b0), "r"(b1));
}

// ---------------------------------------------------------------------------
// Shared core: 128x128x128 tile, 8 warps (4m x 2n), warp tile 32x64.
// acc[mt][nt][4] ; split-bf16 3-term product.
// ---------------------------------------------------------------------------
__device__ __forceinline__ void mma_tile_128(
    const __nv_bfloat16* sAh, const __nv_bfloat16* sAl,
    const __nv_bfloat16* sBh, const __nv_bfloat16* sBl,
    float (&acc)[2][8][4])
{
    const int lane = threadIdx.x & 31;
    const int warp = threadIdx.x >> 5;
    const int wm = warp & 3;       // row group (32 rows)
    const int wn = warp >> 2;      // col group (64 cols)

    #pragma unroll
    for (int mt = 0; mt < 2; ++mt)
        #pragma unroll
        for (int nt = 0; nt < 8; ++nt)
            #pragma unroll
            for (int i = 0; i < 4; ++i) acc[mt][nt][i] = 0.f;

    // A ldmatrix lane addressing (non-trans x4): row = base + (lane&15),
    // col byte = (k0 + 8*(lane>>4))*2
    const int aRow = wm * 32 + (lane & 15);
    const int aCol = 8 * (lane >> 4);
    uint32_t ah[2], al[2];
    ah[0] = smem_u32(&sAh[aRow * SP + aCol]);
    ah[1] = smem_u32(&sAh[(aRow + 16) * SP + aCol]);
    al[0] = smem_u32(&sAl[aRow * SP + aCol]);
    al[1] = smem_u32(&sAl[(aRow + 16) * SP + aCol]);

    // B ldmatrix.trans lane addressing (x4 covers k16 x n16):
    // mat = lane>>3 : (k-half = mat&1, n-half = mat>>1)
    const int bRow = ((lane >> 3) & 1) * 8 + (lane & 7);
    const int bCol = ((lane >> 4) & 1) * 8;
    uint32_t bh[4], bl[4];
    #pragma unroll
    for (int np = 0; np < 4; ++np) {
        const int n0 = wn * 64 + np * 16 + bCol;
        bh[np] = smem_u32(&sBh[bRow * SP + n0]);
        bl[np] = smem_u32(&sBl[bRow * SP + n0]);
    }

    #pragma unroll
    for (int ks = 0; ks < 8; ++ks) {
        uint32_t afh[2][4], afl[2][4];
        ldsm4(afh[0], ah[0]); ldsm4(afh[1], ah[1]);
        ldsm4(afl[0], al[0]); ldsm4(afl[1], al[1]);
        ah[0] += 32; ah[1] += 32; al[0] += 32; al[1] += 32;  // k += 16

        #pragma unroll
        for (int np = 0; np < 4; ++np) {
            uint32_t fbh[4], fbl[4];
            ldsm4t(fbh, bh[np]);
            ldsm4t(fbl, bl[np]);
            bh[np] += 16 * SP * 2;  // k += 16 rows
            bl[np] += 16 * SP * 2;
            #pragma unroll
            for (int mt = 0; mt < 2; ++mt) {
                mma16816(acc[mt][2 * np],     afh[mt], fbh[0], fbh[1]);
                mma16816(acc[mt][2 * np],     afh[mt], fbl[0], fbl[1]);
                mma16816(acc[mt][2 * np],     afl[mt], fbh[0], fbh[1]);
                mma16816(acc[mt][2 * np + 1], afh[mt], fbh[2], fbh[3]);
                mma16816(acc[mt][2 * np + 1], afh[mt], fbl[2], fbl[3]);
                mma16816(acc[mt][2 * np + 1], afl[mt], fbh[2], fbh[3]);
            }
        }
    }
}

#define SMEM_GEMM_BYTES (4 * 128 * SP * 2 + 128 * 4)

// ---------------------------------------------------------------------------
// K0: split all 5 weight matrices into bf16 hi/lo (native [k][n] layout)
// ---------------------------------------------------------------------------
__global__ void prep_weights(const float* __restrict__ Wq,
                             const float* __restrict__ Wk,
                             const float* __restrict__ Wv,
                             const float* __restrict__ Wsk,
                             const float* __restrict__ We)
{
    const float* src[5] = {Wq, Wk, Wv, Wsk, We};
    const int m = blockIdx.y;
    const int i = blockIdx.x * 256 + threadIdx.x;   // 0..16383
    const float v = src[m][i];
    __nv_bfloat16 h, l;
    split_bf16(v, h, l);
    g_Wh[m * 16384 + i] = h;
    g_Wl[m * 16384 + i] = l;
}

// ---------------------------------------------------------------------------
// K1: node GEMMs.  out_j = x @ W_j + b_j for j in {q,k,v,skip}
// ---------------------------------------------------------------------------
__global__ __launch_bounds__(256, 1)
void node_gemm(const float* __restrict__ x,
               const float* __restrict__ bq, const float* __restrict__ bk,
               const float* __restrict__ bv, const float* __restrict__ bsk,
               float* __restrict__ out_skip)
{
    extern __shared__ __align__(16) char smraw[];
    __nv_bfloat16* sAh = (__nv_bfloat16*)smraw;
    __nv_bfloat16* sAl = sAh + 128 * SP;
    __nv_bfloat16* sBh = sAl + 128 * SP;
    __nv_bfloat16* sBl = sBh + 128 * SP;
    float* sb = (float*)(sBl + 128 * SP);

    const int tid = threadIdx.x;
    const int m0  = blockIdx.x * 128;
    const int lane = tid & 31;
    const int warp = tid >> 5;
    const int wm = warp & 3, wn = warp >> 2;

    // Load x tile, convert to hi/lo bf16
    #pragma unroll
    for (int it = 0; it < 16; ++it) {
        const int i4  = tid + it * 256;          // 0..4095
        const int row = i4 >> 5;
        const int k4  = (i4 & 31) * 4;
        const int m   = m0 + row;
        float4 vv = make_float4(0.f, 0.f, 0.f, 0.f);
        if (m < Nn) vv = *(const float4*)(x + (size_t)m * INC + k4);
        __nv_bfloat16 h0, h1, h2, h3, l0, l1, l2, l3;
        split_bf16(vv.x, h0, l0); split_bf16(vv.y, h1, l1);
        split_bf16(vv.z, h2, l2); split_bf16(vv.w, h3, l3);
        __nv_bfloat16* dh = &sAh[row * SP + k4];
        __nv_bfloat16* dl = &sAl[row * SP + k4];
        dh[0] = h0; dh[1] = h1; dh[2] = h2; dh[3] = h3;
        dl[0] = l0; dl[1] = l1; dl[2] = l2; dl[3] = l3;
    }

    const float* bs[4]   = {bq, bk, bv, bsk};
    float*       outs[4] = {g_q, g_k, g_v, out_skip};

    #pragma unroll 1
    for (int j = 0; j < 4; ++j) {
        __syncthreads();
        {   // load weight j hi/lo into smem ([k][n], padded)
            const uint4* srch = (const uint4*)(g_Wh + (size_t)j * 16384);
            const uint4* srcl = (const uint4*)(g_Wl + (size_t)j * 16384);
            #pragma unroll
            for (int it = 0; it < 8; ++it) {
                const int i8  = tid + it * 256;      // 0..2047 (16B chunks)
                const int row = i8 >> 4;
                const int seg = (i8 & 15) * 8;
                *(uint4*)&sBh[row * SP + seg] = srch[row * 16 + (i8 & 15)];
                *(uint4*)&sBl[row * SP + seg] = srcl[row * 16 + (i8 & 15)];
            }
            if (tid < 128) sb[tid] = bs[j][tid];
        }
        __syncthreads();

        float acc[2][8][4];
        mma_tile_128(sAh, sAl, sBh, sBl, acc);

        // epilogue
        float* outp = outs[j];
        const int gid = lane >> 2, tig = lane & 3;
        #pragma unroll
        for (int mt = 0; mt < 2; ++mt) {
            const int r0 = m0 + wm * 32 + mt * 16 + gid;
            #pragma unroll
            for (int nt = 0; nt < 8; ++nt) {
                const int col = wn * 64 + nt * 8 + 2 * tig;
                if (r0 < Nn) {
                    float2 o = make_float2(acc[mt][nt][0] + sb[col],
                                           acc[mt][nt][1] + sb[col + 1]);
                    *(float2*)(outp + (size_t)r0 * OC + col) = o;
                }
                if (r0 + 8 < Nn) {
                    float2 o = make_float2(acc[mt][nt][2] + sb[col],
                                           acc[mt][nt][3] + sb[col + 1]);
                    *(float2*)(outp + (size_t)(r0 + 8) * OC + col) = o;
                }
            }
        }
    }
}

// ---------------------------------------------------------------------------
// K2a: edge GEMM.  attr = [cos(rel_t*wt+bt) | msg] built in smem (bf16 split),
// g_e = attr @ We.  128 edges per block.
// ---------------------------------------------------------------------------
__global__ __launch_bounds__(256, 1)
void edge_gemm(const float* __restrict__ lu, const int* __restrict__ ei,
               const float* __restrict__ tt, const float* __restrict__ msg,
               const float* __restrict__ wt, const float* __restrict__ bt)
{
    extern __shared__ __align__(16) char smraw[];
    __nv_bfloat16* sAh = (__nv_bfloat16*)smraw;
    __nv_bfloat16* sAl = sAh + 128 * SP;
    __nv_bfloat16* sBh = sAl + 128 * SP;
    __nv_bfloat16* sBl = sBh + 128 * SP;
    __shared__ float srel[128];
    __shared__ float swt[64], sbt[64];

    const int tid = threadIdx.x;
    const int e0  = blockIdx.x * 128;
    const int lane = tid & 31;
    const int warp = tid >> 5;
    const int wm = warp & 3, wn = warp >> 2;

    // Load We hi/lo (matrix index 4)
    {
        const uint4* srch = (const uint4*)(g_Wh + (size_t)4 * 16384);
        const uint4* srcl = (const uint4*)(g_Wl + (size_t)4 * 16384);
        #pragma unroll
        for (int it = 0; it < 8; ++it) {
            const int i8  = tid + it * 256;
            const int row = i8 >> 4;
            const int seg = (i8 & 15) * 8;
            *(uint4*)&sBh[row * SP + seg] = srch[row * 16 + (i8 & 15)];
            *(uint4*)&sBl[row * SP + seg] = srcl[row * 16 + (i8 & 15)];
        }
    }
    if (tid < 64) { swt[tid] = wt[tid]; sbt[tid] = bt[tid]; }
    // rel_t per edge
    if (tid >= 128 && tid < 256) {
        const int e = e0 + tid - 128;
        float r = 0.f;
        if (e < Ee) r = lu[ei[e]] - tt[e];
        srel[tid - 128] = r;
    }
    __syncthreads();

    // time-encoding half of attr (cols 0..63)
    #pragma unroll
    for (int i = tid; i < 128 * 64; i += 256) {
        const int eg = i >> 6, d = i & 63;
        const float v = __cosf(srel[eg] * swt[d] + sbt[d]);
        __nv_bfloat16 h, l;
        split_bf16(v, h, l);
        sAh[eg * SP + d] = h;
        sAl[eg * SP + d] = l;
    }
    // msg half of attr (cols 64..127)
    #pragma unroll
    for (int it = 0; it < 8; ++it) {
        const int i4 = tid + it * 256;       // 0..2047
        const int eg = i4 >> 4;
        const int p4 = (i4 & 15) * 4;
        const int e  = e0 + eg;
        float4 vv = make_float4(0.f, 0.f, 0.f, 0.f);
        if (e < Ee) vv = *(const float4*)(msg + (size_t)e * MSGd + p4);
        __nv_bfloat16 h0, h1, h2, h3, l0, l1, l2, l3;
        split_bf16(vv.x, h0, l0); split_bf16(vv.y, h1, l1);
        split_bf16(vv.z, h2, l2); split_bf16(vv.w, h3, l3);
        __nv_bfloat16* dh = &sAh[eg * SP + 64 + p4];
        __nv_bfloat16* dl = &sAl[eg * SP + 64 + p4];
        dh[0] = h0; dh[1] = h1; dh[2] = h2; dh[3] = h3;
        dl[0] = l0; dl[1] = l1; dl[2] = l2; dl[3] = l3;
    }
    __syncthreads();

    float acc[2][8][4];
    mma_tile_128(sAh, sAl, sBh, sBl, acc);

    const int gid = lane >> 2, tig = lane & 3;
    #pragma unroll
    for (int mt = 0; mt < 2; ++mt) {
        const int r0 = e0 + wm * 32 + mt * 16 + gid;
        #pragma unroll
        for (int nt = 0; nt < 8; ++nt) {
            const int col = wn * 64 + nt * 8 + 2 * tig;
            if (r0 < Ee)
                *(float2*)(g_e + (size_t)r0 * OC + col) =
                    make_float2(acc[mt][nt][0], acc[mt][nt][1]);
            if (r0 + 8 < Ee)
                *(float2*)(g_e + (size_t)(r0 + 8) * OC + col) =
                    make_float2(acc[mt][nt][2], acc[mt][nt][3]);
        }
    }
}

// ---------------------------------------------------------------------------
// K2b: per-edge attention + scatter.  One warp per edge.
// ---------------------------------------------------------------------------
__global__ __launch_bounds__(256)
void edge_attn(const int* __restrict__ ei)
{
    const int gw   = (blockIdx.x * blockDim.x + threadIdx.x) >> 5;
    const int lane = threadIdx.x & 31;
    if (gw >= Ee) return;
    const int e   = gw;
    const int src = ei[e];
    const int dst = ei[Ee + e];

    const float4 e4 = __ldcs((const float4*)(g_e + (size_t)e * OC + lane * 4));
    const float4 k4 = *(const float4*)(g_k + (size_t)src * OC + lane * 4);
    const float4 v4 = *(const float4*)(g_v + (size_t)src * OC + lane * 4);
    const float4 q4 = *(const float4*)(g_q + (size_t)dst * OC + lane * 4);

    const float kjx = k4.x + e4.x, kjy = k4.y + e4.y;
    const float kjz = k4.z + e4.z, kjw = k4.w + e4.w;

    float p = q4.x * kjx + q4.y * kjy + q4.z * kjz + q4.w * kjw;
    p += __shfl_xor_sync(0xffffffffu, p, 8);
    p += __shfl_xor_sync(0xffffffffu, p, 4);
    p += __shfl_xor_sync(0xffffffffu, p, 2);
    p += __shfl_xor_sync(0xffffffffu, p, 1);

    const float w = __expf(p * 0.125f);   // 1/sqrt(64)

    if ((lane & 15) == 0)
        atomicAdd(&g_denom[2 * dst + (lane >> 4)], w);

    float* ap = g_acc + (size_t)dst * OC + lane * 4;
    const float wx = w * (v4.x + e4.x);
    const float wy = w * (v4.y + e4.y);
    const float wz = w * (v4.z + e4.z);
    const float ww = w * (v4.w + e4.w);
    asm volatile("red.global.add.v4.f32 [%0], {%1, %2, %3, %4};"
                 :: "l"(ap), "f"(wx), "f"(wy), "f"(wz), "f"(ww) : "memory");
}

// ---------------------------------------------------------------------------
// K3: out = g_acc / (denom + 1e-16) + skip (skip already in d_out from K1)
// ---------------------------------------------------------------------------
__global__ __launch_bounds__(256)
void finalize(float* __restrict__ out)
{
    const int i = blockIdx.x * blockDim.x + threadIdx.x;   // float4 index
    if (i >= Nn * OC / 4) return;
    const int n = i >> 5;
    const int h = (i >> 4) & 1;
    const float inv = 1.f / (g_denom[2 * n + h] + 1e-16f);
    float4 a = ((const float4*)g_acc)[i];
    float4 o = ((float4*)out)[i];
    o.x += a.x * inv;
    o.y += a.y * inv;
    o.z += a.z * inv;
    o.w += a.w * inv;
    ((float4*)out)[i] = o;
}

// ---------------------------------------------------------------------------
extern "C" void kernel_launch(void* const* d_in, const int* in_sizes, int n_in,
                              void* d_out, int out_size)
{
    const float* x    = (const float*)d_in[0];
    const float* lu   = (const float*)d_in[1];
    const int*   ei   = (const int*)  d_in[2];
    const float* tt   = (const float*)d_in[3];
    const float* msg  = (const float*)d_in[4];
    const float* wt   = (const float*)d_in[5];
    const float* bt   = (const float*)d_in[6];
    const float* Wq   = (const float*)d_in[7];
    const float* bq   = (const float*)d_in[8];
    const float* Wk   = (const float*)d_in[9];
    const float* bk   = (const float*)d_in[10];
    const float* Wv   = (const float*)d_in[11];
    const float* bv   = (const float*)d_in[12];
    const float* We   = (const float*)d_in[13];
    const float* Wsk  = (const float*)d_in[14];
    const float* bsk  = (const float*)d_in[15];
    float* out = (float*)d_out;

    cudaFuncSetAttribute(node_gemm, cudaFuncAttributeMaxDynamicSharedMemorySize, SMEM_GEMM_BYTES);
    cudaFuncSetAttribute(edge_gemm, cudaFuncAttributeMaxDynamicSharedMemorySize, SMEM_GEMM_BYTES);

    void* accp = nullptr;
    void* denp = nullptr;
    cudaGetSymbolAddress(&accp, g_acc);
    cudaGetSymbolAddress(&denp, g_denom);
    cudaMemsetAsync(accp, 0, (size_t)Nn * OC * sizeof(float));
    cudaMemsetAsync(denp, 0, (size_t)Nn * Hh * sizeof(float));

    dim3 pg(64, 5);
    prep_weights<<<pg, 256>>>(Wq, Wk, Wv, Wsk, We);

    node_gemm<<<(Nn + 127) / 128, 256, SMEM_GEMM_BYTES>>>(
        x, bq, bk, bv, bsk, out);

    edge_gemm<<<(Ee + 127) / 128, 256, SMEM_GEMM_BYTES>>>(
        lu, ei, tt, msg, wt, bt);

    edge_attn<<<(Ee * 32 + 255) / 256, 256>>>(ei);

    finalize<<<(Nn * OC / 4 + 255) / 256, 256>>>(out);
}

// round 7
// speedup vs baseline: 2.0503x; 1.0280x over previous
#include <cuda_runtime.h>
#include <cuda_bf16.h>
#include <math.h>
#include <stdint.h>

// Problem constants (fixed shapes from reference)
#define Nn   100000
#define Ee   600000
#define INC  128
#define OC   128     // H*C
#define Hh   2
#define MSGd 64
#define Td   64

#define SP   136     // smem bf16 row stride (272B: conflict-free ldmatrix)

// ---------------- scratch (device globals; no runtime alloc) ----------------
__device__ __align__(16) float g_q[(size_t)Nn * OC];
__device__ __align__(16) float g_k[(size_t)Nn * OC];
__device__ __align__(16) float g_v[(size_t)Nn * OC];
__device__ __align__(16) float g_e[(size_t)Ee * OC];
__device__ __align__(16) float g_acc[(size_t)Nn * OC];
__device__ float g_denom[(size_t)Nn * Hh];
// bf16 hi/lo split weights, native [k][n] layout: Wq,Wk,Wv,Wskip,We
__device__ __align__(16) __nv_bfloat16 g_Wh[5 * 128 * 128];
__device__ __align__(16) __nv_bfloat16 g_Wl[5 * 128 * 128];

// ---------------------------------------------------------------------------
// helpers
// ---------------------------------------------------------------------------
__device__ __forceinline__ uint32_t smem_u32(const void* p)
{
    return (uint32_t)__cvta_generic_to_shared(p);
}

__device__ __forceinline__ void split_bf16(float v, __nv_bfloat16& h, __nv_bfloat16& l)
{
    h = __float2bfloat16(v);
    l = __float2bfloat16(v - __bfloat162float(h));
}

__device__ __forceinline__ void ldsm4(uint32_t* r, uint32_t a)
{
    asm volatile("ldmatrix.sync.aligned.m8n8.x4.shared.b16 {%0,%1,%2,%3},[%4];"
                 : "=r"(r[0]), "=r"(r[1]), "=r"(r[2]), "=r"(r[3]) : "r"(a));
}
__device__ __forceinline__ void ldsm4t(uint32_t* r, uint32_t a)
{
    asm volatile("ldmatrix.sync.aligned.m8n8.x4.trans.shared.b16 {%0,%1,%2,%3},[%4];"
                 : "=r"(r[0]), "=r"(r[1]), "=r"(r[2]), "=r"(r[3]) : "r"(a));
}
__device__ __forceinline__ void mma16816(float* c, const uint32_t* a,
                                         uint32_t b0, uint32_t b1)
{
    asm volatile(
        "mma.sync.aligned.m16n8k16.row.col.f32.bf16.bf16.f32 "
        "{%0,%1,%2,%3},{%4,%5,%6,%7},{%8,%9},{%0,%1,%2,%3};"
        : "+f"(c[0]), "+f"(c[1]), "+f"(c[2]), "+f"(c[3])
        : "r"(a[0]), "r"(a[1]), "r"(a[2]), "r"(a[3]), "r"(b0), "r"(b1));
}

// ---------------------------------------------------------------------------
// Core: 128x128x128 tile, 16 warps (4m x 4n), warp tile 32x32.
// Split-bf16 3-term product; 2-stage fragment double-buffer over k-steps.
// ---------------------------------------------------------------------------
__device__ __forceinline__ void mma_tile_512(
    const __nv_bfloat16* sAh, const __nv_bfloat16* sAl,
    const __nv_bfloat16* sBh, const __nv_bfloat16* sBl,
    float (&acc)[2][4][4])
{
    const int lane = threadIdx.x & 31;
    const int warp = threadIdx.x >> 5;
    const int wm = warp & 3;       // row group (32 rows)
    const int wn = warp >> 2;      // col group (32 cols)

    #pragma unroll
    for (int mt = 0; mt < 2; ++mt)
        #pragma unroll
        for (int j = 0; j < 4; ++j)
            #pragma unroll
            for (int i = 0; i < 4; ++i) acc[mt][j][i] = 0.f;

    // A ldmatrix (non-trans x4, 16r x 16k): row = base+(lane&15), col 8*(lane>>4)
    const int aRow = wm * 32 + (lane & 15);
    const int aCol = 8 * (lane >> 4);
    uint32_t ah[2], al[2];
    #pragma unroll
    for (int mt = 0; mt < 2; ++mt) {
        ah[mt] = smem_u32(&sAh[(aRow + 16 * mt) * SP + aCol]);
        al[mt] = smem_u32(&sAl[(aRow + 16 * mt) * SP + aCol]);
    }

    // B ldmatrix.trans (x4 covers k16 x n16)
    const int bRow = ((lane >> 3) & 1) * 8 + (lane & 7);
    const int bCol = ((lane >> 4) & 1) * 8;
    uint32_t bh[2], bl[2];
    #pragma unroll
    for (int np = 0; np < 2; ++np) {
        const int n0 = wn * 32 + np * 16 + bCol;
        bh[np] = smem_u32(&sBh[bRow * SP + n0]);
        bl[np] = smem_u32(&sBl[bRow * SP + n0]);
    }

    // two-stage fragment buffers
    uint32_t Fah[2][2][4], Fal[2][2][4], Fbh[2][2][4], Fbl[2][2][4];

    #define LOAD_STAGE(s, ks) do {                                         \
        _Pragma("unroll")                                                  \
        for (int mt = 0; mt < 2; ++mt) {                                   \
            ldsm4(Fah[s][mt], ah[mt] + (ks) * 32);                         \
            ldsm4(Fal[s][mt], al[mt] + (ks) * 32);                         \
        }                                                                  \
        _Pragma("unroll")                                                  \
        for (int np = 0; np < 2; ++np) {                                   \
            ldsm4t(Fbh[s][np], bh[np] + (ks) * 16 * SP * 2);               \
            ldsm4t(Fbl[s][np], bl[np] + (ks) * 16 * SP * 2);               \
        }                                                                  \
    } while (0)

    LOAD_STAGE(0, 0);

    #pragma unroll
    for (int ks = 0; ks < 8; ++ks) {
        const int s = ks & 1;
        if (ks < 7) LOAD_STAGE(s ^ 1, ks + 1);
        #pragma unroll
        for (int np = 0; np < 2; ++np)
            #pragma unroll
            for (int mt = 0; mt < 2; ++mt) {
                mma16816(acc[mt][2 * np],     Fah[s][mt], Fbh[s][np][0], Fbh[s][np][1]);
                mma16816(acc[mt][2 * np],     Fah[s][mt], Fbl[s][np][0], Fbl[s][np][1]);
                mma16816(acc[mt][2 * np],     Fal[s][mt], Fbh[s][np][0], Fbh[s][np][1]);
                mma16816(acc[mt][2 * np + 1], Fah[s][mt], Fbh[s][np][2], Fbh[s][np][3]);
                mma16816(acc[mt][2 * np + 1], Fah[s][mt], Fbl[s][np][2], Fbl[s][np][3]);
                mma16816(acc[mt][2 * np + 1], Fal[s][mt], Fbh[s][np][2], Fbh[s][np][3]);
            }
    }
    #undef LOAD_STAGE
}

#define SMEM_GEMM_BYTES (4 * 128 * SP * 2 + 128 * 4)

// ---------------------------------------------------------------------------
// K0: split all 5 weight matrices into bf16 hi/lo (native [k][n] layout)
// ---------------------------------------------------------------------------
__global__ void prep_weights(const float* __restrict__ Wq,
                             const float* __restrict__ Wk,
                             const float* __restrict__ Wv,
                             const float* __restrict__ Wsk,
                             const float* __restrict__ We)
{
    const float* src[5] = {Wq, Wk, Wv, Wsk, We};
    const int m = blockIdx.y;
    const int i = blockIdx.x * 256 + threadIdx.x;   // 0..16383
    const float v = src[m][i];
    __nv_bfloat16 h, l;
    split_bf16(v, h, l);
    g_Wh[m * 16384 + i] = h;
    g_Wl[m * 16384 + i] = l;
}

// ---------------------------------------------------------------------------
// K1: node GEMMs.  out_j = x @ W_j + b_j for j in {q,k,v,skip}
// ---------------------------------------------------------------------------
__global__ __launch_bounds__(512, 1)
void node_gemm(const float* __restrict__ x,
               const float* __restrict__ bq, const float* __restrict__ bk,
               const float* __restrict__ bv, const float* __restrict__ bsk,
               float* __restrict__ out_skip)
{
    extern __shared__ __align__(16) char smraw[];
    __nv_bfloat16* sAh = (__nv_bfloat16*)smraw;
    __nv_bfloat16* sAl = sAh + 128 * SP;
    __nv_bfloat16* sBh = sAl + 128 * SP;
    __nv_bfloat16* sBl = sBh + 128 * SP;
    float* sb = (float*)(sBl + 128 * SP);

    const int tid = threadIdx.x;
    const int m0  = blockIdx.x * 128;
    const int lane = tid & 31;
    const int warp = tid >> 5;
    const int wm = warp & 3, wn = warp >> 2;

    // Load x tile, convert to hi/lo bf16
    #pragma unroll
    for (int it = 0; it < 8; ++it) {
        const int i4  = tid + it * 512;          // 0..4095
        const int row = i4 >> 5;
        const int k4  = (i4 & 31) * 4;
        const int m   = m0 + row;
        float4 vv = make_float4(0.f, 0.f, 0.f, 0.f);
        if (m < Nn) vv = *(const float4*)(x + (size_t)m * INC + k4);
        __nv_bfloat16 h0, h1, h2, h3, l0, l1, l2, l3;
        split_bf16(vv.x, h0, l0); split_bf16(vv.y, h1, l1);
        split_bf16(vv.z, h2, l2); split_bf16(vv.w, h3, l3);
        __nv_bfloat16* dh = &sAh[row * SP + k4];
        __nv_bfloat16* dl = &sAl[row * SP + k4];
        dh[0] = h0; dh[1] = h1; dh[2] = h2; dh[3] = h3;
        dl[0] = l0; dl[1] = l1; dl[2] = l2; dl[3] = l3;
    }

    const float* bs[4]   = {bq, bk, bv, bsk};
    float*       outs[4] = {g_q, g_k, g_v, out_skip};

    #pragma unroll 1
    for (int j = 0; j < 4; ++j) {
        __syncthreads();
        {   // load weight j hi/lo into smem ([k][n], padded)
            const uint4* srch = (const uint4*)(g_Wh + (size_t)j * 16384);
            const uint4* srcl = (const uint4*)(g_Wl + (size_t)j * 16384);
            #pragma unroll
            for (int it = 0; it < 4; ++it) {
                const int i8  = tid + it * 512;      // 0..2047 (16B chunks)
                const int row = i8 >> 4;
                const int seg = (i8 & 15) * 8;
                *(uint4*)&sBh[row * SP + seg] = srch[row * 16 + (i8 & 15)];
                *(uint4*)&sBl[row * SP + seg] = srcl[row * 16 + (i8 & 15)];
            }
            if (tid < 128) sb[tid] = bs[j][tid];
        }
        __syncthreads();

        float acc[2][4][4];
        mma_tile_512(sAh, sAl, sBh, sBl, acc);

        // epilogue
        float* outp = outs[j];
        const int gid = lane >> 2, tig = lane & 3;
        #pragma unroll
        for (int mt = 0; mt < 2; ++mt) {
            const int r0 = m0 + wm * 32 + mt * 16 + gid;
            #pragma unroll
            for (int nt = 0; nt < 4; ++nt) {
                const int col = wn * 32 + nt * 8 + 2 * tig;
                if (r0 < Nn) {
                    float2 o = make_float2(acc[mt][nt][0] + sb[col],
                                           acc[mt][nt][1] + sb[col + 1]);
                    *(float2*)(outp + (size_t)r0 * OC + col) = o;
                }
                if (r0 + 8 < Nn) {
                    float2 o = make_float2(acc[mt][nt][2] + sb[col],
                                           acc[mt][nt][3] + sb[col + 1]);
                    *(float2*)(outp + (size_t)(r0 + 8) * OC + col) = o;
                }
            }
        }
    }
}

// ---------------------------------------------------------------------------
// K2a: edge GEMM.  attr = [cos(rel_t*wt+bt) | msg] built in smem (bf16 split),
// g_e = attr @ We.  128 edges per block.
// ---------------------------------------------------------------------------
__global__ __launch_bounds__(512, 1)
void edge_gemm(const float* __restrict__ lu, const int* __restrict__ ei,
               const float* __restrict__ tt, const float* __restrict__ msg,
               const float* __restrict__ wt, const float* __restrict__ bt)
{
    extern __shared__ __align__(16) char smraw[];
    __nv_bfloat16* sAh = (__nv_bfloat16*)smraw;
    __nv_bfloat16* sAl = sAh + 128 * SP;
    __nv_bfloat16* sBh = sAl + 128 * SP;
    __nv_bfloat16* sBl = sBh + 128 * SP;
    __shared__ float srel[128];
    __shared__ float swt[64], sbt[64];

    const int tid = threadIdx.x;
    const int e0  = blockIdx.x * 128;
    const int lane = tid & 31;
    const int warp = tid >> 5;
    const int wm = warp & 3, wn = warp >> 2;

    // Load We hi/lo (matrix index 4)
    {
        const uint4* srch = (const uint4*)(g_Wh + (size_t)4 * 16384);
        const uint4* srcl = (const uint4*)(g_Wl + (size_t)4 * 16384);
        #pragma unroll
        for (int it = 0; it < 4; ++it) {
            const int i8  = tid + it * 512;
            const int row = i8 >> 4;
            const int seg = (i8 & 15) * 8;
            *(uint4*)&sBh[row * SP + seg] = srch[row * 16 + (i8 & 15)];
            *(uint4*)&sBl[row * SP + seg] = srcl[row * 16 + (i8 & 15)];
        }
    }
    if (tid < 64) { swt[tid] = wt[tid]; sbt[tid] = bt[tid]; }
    if (tid >= 128 && tid < 256) {
        const int e = e0 + tid - 128;
        float r = 0.f;
        if (e < Ee) r = lu[ei[e]] - tt[e];
        srel[tid - 128] = r;
    }
    __syncthreads();

    // time-encoding half of attr (cols 0..63)
    #pragma unroll
    for (int i = tid; i < 128 * 64; i += 512) {
        const int eg = i >> 6, d = i & 63;
        const float v = __cosf(srel[eg] * swt[d] + sbt[d]);
        __nv_bfloat16 h, l;
        split_bf16(v, h, l);
        sAh[eg * SP + d] = h;
        sAl[eg * SP + d] = l;
    }
    // msg half of attr (cols 64..127)
    #pragma unroll
    for (int it = 0; it < 4; ++it) {
        const int i4 = tid + it * 512;       // 0..2047
        const int eg = i4 >> 4;
        const int p4 = (i4 & 15) * 4;
        const int e  = e0 + eg;
        float4 vv = make_float4(0.f, 0.f, 0.f, 0.f);
        if (e < Ee) vv = *(const float4*)(msg + (size_t)e * MSGd + p4);
        __nv_bfloat16 h0, h1, h2, h3, l0, l1, l2, l3;
        split_bf16(vv.x, h0, l0); split_bf16(vv.y, h1, l1);
        split_bf16(vv.z, h2, l2); split_bf16(vv.w, h3, l3);
        __nv_bfloat16* dh = &sAh[eg * SP + 64 + p4];
        __nv_bfloat16* dl = &sAl[eg * SP + 64 + p4];
        dh[0] = h0; dh[1] = h1; dh[2] = h2; dh[3] = h3;
        dl[0] = l0; dl[1] = l1; dl[2] = l2; dl[3] = l3;
    }
    __syncthreads();

    float acc[2][4][4];
    mma_tile_512(sAh, sAl, sBh, sBl, acc);

    const int gid = lane >> 2, tig = lane & 3;
    #pragma unroll
    for (int mt = 0; mt < 2; ++mt) {
        const int r0 = e0 + wm * 32 + mt * 16 + gid;
        #pragma unroll
        for (int nt = 0; nt < 4; ++nt) {
            const int col = wn * 32 + nt * 8 + 2 * tig;
            if (r0 < Ee)
                *(float2*)(g_e + (size_t)r0 * OC + col) =
                    make_float2(acc[mt][nt][0], acc[mt][nt][1]);
            if (r0 + 8 < Ee)
                *(float2*)(g_e + (size_t)(r0 + 8) * OC + col) =
                    make_float2(acc[mt][nt][2], acc[mt][nt][3]);
        }
    }
}

// ---------------------------------------------------------------------------
// K2b: per-edge attention + scatter.  One warp per edge.
// ---------------------------------------------------------------------------
__global__ __launch_bounds__(256)
void edge_attn(const int* __restrict__ ei)
{
    const int gw   = (blockIdx.x * blockDim.x + threadIdx.x) >> 5;
    const int lane = threadIdx.x & 31;
    if (gw >= Ee) return;
    const int e   = gw;
    const int src = ei[e];
    const int dst = ei[Ee + e];

    const float4 e4 = __ldcs((const float4*)(g_e + (size_t)e * OC + lane * 4));
    const float4 k4 = *(const float4*)(g_k + (size_t)src * OC + lane * 4);
    const float4 v4 = *(const float4*)(g_v + (size_t)src * OC + lane * 4);
    const float4 q4 = *(const float4*)(g_q + (size_t)dst * OC + lane * 4);

    const float kjx = k4.x + e4.x, kjy = k4.y + e4.y;
    const float kjz = k4.z + e4.z, kjw = k4.w + e4.w;

    float p = q4.x * kjx + q4.y * kjy + q4.z * kjz + q4.w * kjw;
    p += __shfl_xor_sync(0xffffffffu, p, 8);
    p += __shfl_xor_sync(0xffffffffu, p, 4);
    p += __shfl_xor_sync(0xffffffffu, p, 2);
    p += __shfl_xor_sync(0xffffffffu, p, 1);

    const float w = __expf(p * 0.125f);   // 1/sqrt(64)

    if ((lane & 15) == 0)
        atomicAdd(&g_denom[2 * dst + (lane >> 4)], w);

    float* ap = g_acc + (size_t)dst * OC + lane * 4;
    const float wx = w * (v4.x + e4.x);
    const float wy = w * (v4.y + e4.y);
    const float wz = w * (v4.z + e4.z);
    const float ww = w * (v4.w + e4.w);
    asm volatile("red.global.add.v4.f32 [%0], {%1, %2, %3, %4};"
                 :: "l"(ap), "f"(wx), "f"(wy), "f"(wz), "f"(ww) : "memory");
}

// ---------------------------------------------------------------------------
// K3: out = g_acc / (denom + 1e-16) + skip (skip already in d_out from K1)
// ---------------------------------------------------------------------------
__global__ __launch_bounds__(256)
void finalize(float* __restrict__ out)
{
    const int i = blockIdx.x * blockDim.x + threadIdx.x;   // float4 index
    if (i >= Nn * OC / 4) return;
    const int n = i >> 5;
    const int h = (i >> 4) & 1;
    const float inv = 1.f / (g_denom[2 * n + h] + 1e-16f);
    float4 a = ((const float4*)g_acc)[i];
    float4 o = ((float4*)out)[i];
    o.x += a.x * inv;
    o.y += a.y * inv;
    o.z += a.z * inv;
    o.w += a.w * inv;
    ((float4*)out)[i] = o;
}

// ---------------------------------------------------------------------------
extern "C" void kernel_launch(void* const* d_in, const int* in_sizes, int n_in,
                              void* d_out, int out_size)
{
    const float* x    = (const float*)d_in[0];
    const float* lu   = (const float*)d_in[1];
    const int*   ei   = (const int*)  d_in[2];
    const float* tt   = (const float*)d_in[3];
    const float* msg  = (const float*)d_in[4];
    const float* wt   = (const float*)d_in[5];
    const float* bt   = (const float*)d_in[6];
    const float* Wq   = (const float*)d_in[7];
    const float* bq   = (const float*)d_in[8];
    const float* Wk   = (const float*)d_in[9];
    const float* bk   = (const float*)d_in[10];
    const float* Wv   = (const float*)d_in[11];
    const float* bv   = (const float*)d_in[12];
    const float* We   = (const float*)d_in[13];
    const float* Wsk  = (const float*)d_in[14];
    const float* bsk  = (const float*)d_in[15];
    float* out = (float*)d_out;

    cudaFuncSetAttribute(node_gemm, cudaFuncAttributeMaxDynamicSharedMemorySize, SMEM_GEMM_BYTES);
    cudaFuncSetAttribute(edge_gemm, cudaFuncAttributeMaxDynamicSharedMemorySize, SMEM_GEMM_BYTES);

    void* accp = nullptr;
    void* denp = nullptr;
    cudaGetSymbolAddress(&accp, g_acc);
    cudaGetSymbolAddress(&denp, g_denom);
    cudaMemsetAsync(accp, 0, (size_t)Nn * OC * sizeof(float));
    cudaMemsetAsync(denp, 0, (size_t)Nn * Hh * sizeof(float));

    dim3 pg(64, 5);
    prep_weights<<<pg, 256>>>(Wq, Wk, Wv, Wsk, We);

    node_gemm<<<(Nn + 127) / 128, 512, SMEM_GEMM_BYTES>>>(
        x, bq, bk, bv, bsk, out);

    edge_gemm<<<(Ee + 127) / 128, 512, SMEM_GEMM_BYTES>>>(
        lu, ei, tt, msg, wt, bt);

    edge_attn<<<(Ee * 32 + 255) / 256, 256>>>(ei);

    finalize<<<(Nn * OC / 4 + 255) / 256, 256>>>(out);
}